// round 1
// baseline (speedup 1.0000x reference)
#include <cuda_runtime.h>
#include <math.h>

#define NN 100000
#define NE 1600000

// ---------------- scratch (static __device__ — no allocations) ----------------
__device__ int g_deg[NN];
__device__ int g_start[NN];
__device__ int g_cursor[NN];
__device__ int g_csr[NE];
__device__ int g_bsum[128];                 // ceil(100000/1024)=98 block sums
__device__ float g_agg[NN * 64];
__device__ float g_hA[NN * 64];
__device__ float g_hB[NN * 64];

// ---------------- CSR build ----------------
__global__ void k_zero_deg() {
    int i = blockIdx.x * blockDim.x + threadIdx.x;
    if (i < NN) g_deg[i] = 0;
}

__global__ void k_count(const int* __restrict__ dst) {
    int e = blockIdx.x * blockDim.x + threadIdx.x;
    if (e < NE) atomicAdd(&g_deg[dst[e]], 1);
}

__global__ void k_scan_local() {
    __shared__ int s[1024];
    int tid = threadIdx.x;
    int i = blockIdx.x * 1024 + tid;
    int v = (i < NN) ? g_deg[i] : 0;
    s[tid] = v;
    __syncthreads();
    for (int off = 1; off < 1024; off <<= 1) {
        int t = (tid >= off) ? s[tid - off] : 0;
        __syncthreads();
        s[tid] += t;
        __syncthreads();
    }
    if (i < NN) g_start[i] = s[tid] - v;        // local exclusive
    if (tid == 1023) g_bsum[blockIdx.x] = s[1023];
}

__global__ void k_scan_bsum(int nb) {
    if (threadIdx.x == 0 && blockIdx.x == 0) {
        int acc = 0;
        for (int b = 0; b < nb; b++) { int t = g_bsum[b]; g_bsum[b] = acc; acc += t; }
    }
}

__global__ void k_scan_add() {
    int i = blockIdx.x * blockDim.x + threadIdx.x;
    if (i < NN) {
        int s = g_start[i] + g_bsum[i >> 10];
        g_start[i] = s;
        g_cursor[i] = s;
    }
}

__global__ void k_fill(const int* __restrict__ src, const int* __restrict__ dst) {
    int e = blockIdx.x * blockDim.x + threadIdx.x;
    if (e < NE) {
        int d = dst[e];
        int p = atomicAdd(&g_cursor[d], 1);
        g_csr[p] = src[e];
    }
}

// ---------------- mean aggregation (gather, no atomics) ----------------
// 16 (or 8) threads per node, each accumulates one float4 of the feature row.
template <int D>
__global__ __launch_bounds__(256) void k_gather(const float* __restrict__ hin,
                                                float* __restrict__ agg) {
    constexpr int C = D / 4;                    // float4 chunks per row
    int gid = blockIdx.x * blockDim.x + threadIdx.x;
    int n = gid / C;
    int c = gid % C;
    if (n >= NN) return;
    int st = g_start[n];
    int dg = g_deg[n];
    const float4* h4 = (const float4*)hin;
    float4 acc = make_float4(0.f, 0.f, 0.f, 0.f);
    for (int i = st; i < st + dg; i++) {
        int s = g_csr[i];
        float4 v = h4[s * C + c];
        acc.x += v.x; acc.y += v.y; acc.z += v.z; acc.w += v.w;
    }
    float inv = dg > 0 ? 1.f / (float)dg : 0.f;
    acc.x *= inv; acc.y *= inv; acc.z *= inv; acc.w *= inv;
    ((float4*)agg)[n * C + c] = acc;
}

// ---------------- SAGE transform: out = act(agg@Wn + bn + hin@Wr) ----------------
// 256 threads, 16 nodes per group iteration; thread (ln,lane) computes
// outputs [4*lane .. 4*lane+3] of node ln via LDS.128 weight loads.
template <int DIN, bool RELU>
__global__ __launch_bounds__(256) void k_transform(const float* __restrict__ agg,
                                                   const float* __restrict__ hin,
                                                   const float* __restrict__ Wn,
                                                   const float* __restrict__ bn,
                                                   const float* __restrict__ Wr,
                                                   float* __restrict__ hout) {
    constexpr int STR = DIN + 8;                // padded row stride (keeps 16B align, avoids bank conflicts)
    constexpr int CIN = DIN / 4;
    __shared__ __align__(16) float sWn[DIN * 64];
    __shared__ __align__(16) float sWr[DIN * 64];
    __shared__ __align__(16) float sbn[64];
    __shared__ __align__(16) float sA[16 * STR];
    __shared__ __align__(16) float sH[16 * STR];

    int tid = threadIdx.x;
    for (int idx = tid; idx < DIN * 64; idx += 256) { sWn[idx] = Wn[idx]; sWr[idx] = Wr[idx]; }
    if (tid < 64) sbn[tid] = bn[tid];

    int lane = tid & 15;
    int ln = tid >> 4;
    const int ngroups = NN / 16;                // 100000 % 16 == 0

    for (int g = blockIdx.x; g < ngroups; g += gridDim.x) {
        int n = g * 16 + ln;
        __syncthreads();                        // protects weights (iter 0) and staging reuse
        if (lane < CIN) {
            float4 a = ((const float4*)agg)[n * CIN + lane];
            *(float4*)&sA[ln * STR + lane * 4] = a;
            float4 h = ((const float4*)hin)[n * CIN + lane];
            *(float4*)&sH[ln * STR + lane * 4] = h;
        }
        __syncthreads();

        float4 acc = *(const float4*)&sbn[lane * 4];
#pragma unroll
        for (int k = 0; k < DIN; k++) {
            float a = sA[ln * STR + k];
            float4 w = *(const float4*)&sWn[k * 64 + lane * 4];
            acc.x += a * w.x; acc.y += a * w.y; acc.z += a * w.z; acc.w += a * w.w;
            float h = sH[ln * STR + k];
            float4 wr = *(const float4*)&sWr[k * 64 + lane * 4];
            acc.x += h * wr.x; acc.y += h * wr.y; acc.z += h * wr.z; acc.w += h * wr.w;
        }
        if (RELU) {
            acc.x = fmaxf(acc.x, 0.f); acc.y = fmaxf(acc.y, 0.f);
            acc.z = fmaxf(acc.z, 0.f); acc.w = fmaxf(acc.w, 0.f);
        }
        ((float4*)hout)[n * 16 + lane] = acc;
    }
}

// ---------------- predictor head: sigmoid(relu(h@Wp1+bp1)@Wp2+bp2) ----------------
__global__ __launch_bounds__(256) void k_head(const float* __restrict__ h,
                                              const float* __restrict__ Wp1,
                                              const float* __restrict__ bp1,
                                              const float* __restrict__ Wp2,
                                              const float* __restrict__ bp2,
                                              float* __restrict__ out) {
    constexpr int STR = 72;
    __shared__ __align__(16) float sW[64 * 64];
    __shared__ __align__(16) float sb[64];
    __shared__ __align__(16) float sw2[64];
    __shared__ __align__(16) float sH[16 * STR];

    int tid = threadIdx.x;
    for (int idx = tid; idx < 64 * 64; idx += 256) sW[idx] = Wp1[idx];
    if (tid < 64) { sb[tid] = bp1[tid]; sw2[tid] = Wp2[tid]; }
    float b2 = bp2[0];

    int lane = tid & 15;
    int ln = tid >> 4;
    const int ngroups = NN / 16;

    for (int g = blockIdx.x; g < ngroups; g += gridDim.x) {
        int n = g * 16 + ln;
        __syncthreads();
        float4 hv = ((const float4*)h)[n * 16 + lane];
        *(float4*)&sH[ln * STR + lane * 4] = hv;
        __syncthreads();

        float4 p = *(const float4*)&sb[lane * 4];
#pragma unroll
        for (int k = 0; k < 64; k++) {
            float x = sH[ln * STR + k];
            float4 w = *(const float4*)&sW[k * 64 + lane * 4];
            p.x += x * w.x; p.y += x * w.y; p.z += x * w.z; p.w += x * w.w;
        }
        p.x = fmaxf(p.x, 0.f); p.y = fmaxf(p.y, 0.f);
        p.z = fmaxf(p.z, 0.f); p.w = fmaxf(p.w, 0.f);
        float4 w2 = *(const float4*)&sw2[lane * 4];
        float part = p.x * w2.x + p.y * w2.y + p.z * w2.z + p.w * w2.w;
#pragma unroll
        for (int o = 8; o >= 1; o >>= 1)
            part += __shfl_xor_sync(0xffffffffu, part, o);
        if (lane == 0) out[n] = 1.f / (1.f + expf(-(part + b2)));
    }
}

// ---------------- launch ----------------
extern "C" void kernel_launch(void* const* d_in, const int* in_sizes, int n_in,
                              void* d_out, int out_size) {
    const float* x   = (const float*)d_in[0];
    const int*   ei  = (const int*)d_in[1];
    const int*   src = ei;
    const int*   dst = ei + NE;
    const float* Wn0 = (const float*)d_in[2];
    const float* bn0 = (const float*)d_in[3];
    const float* Wr0 = (const float*)d_in[4];
    const float* Wn1 = (const float*)d_in[5];
    const float* bn1 = (const float*)d_in[6];
    const float* Wr1 = (const float*)d_in[7];
    const float* Wn2 = (const float*)d_in[8];
    const float* bn2 = (const float*)d_in[9];
    const float* Wr2 = (const float*)d_in[10];
    const float* Wp1 = (const float*)d_in[11];
    const float* bp1 = (const float*)d_in[12];
    const float* Wp2 = (const float*)d_in[13];
    const float* bp2 = (const float*)d_in[14];
    float* out = (float*)d_out;

    float* agg; cudaGetSymbolAddress((void**)&agg, g_agg);
    float* hA;  cudaGetSymbolAddress((void**)&hA,  g_hA);
    float* hB;  cudaGetSymbolAddress((void**)&hB,  g_hB);

    const int TB = 256;
    // CSR build
    k_zero_deg<<<(NN + TB - 1) / TB, TB>>>();
    k_count<<<(NE + TB - 1) / TB, TB>>>(dst);
    k_scan_local<<<(NN + 1023) / 1024, 1024>>>();
    k_scan_bsum<<<1, 32>>>((NN + 1023) / 1024);
    k_scan_add<<<(NN + TB - 1) / TB, TB>>>();
    k_fill<<<(NE + TB - 1) / TB, TB>>>(src, dst);

    const int GRID_T = 888;   // 148 SMs * 6, grid-stride over 6250 node groups

    // layer 0: IN=32 -> 64, relu
    k_gather<32><<<(NN * 8 + TB - 1) / TB, TB>>>(x, agg);
    k_transform<32, true><<<GRID_T, TB>>>(agg, x, Wn0, bn0, Wr0, hA);
    // layer 1: 64 -> 64, relu
    k_gather<64><<<(NN * 16 + TB - 1) / TB, TB>>>(hA, agg);
    k_transform<64, true><<<GRID_T, TB>>>(agg, hA, Wn1, bn1, Wr1, hB);
    // layer 2: 64 -> 64, no act
    k_gather<64><<<(NN * 16 + TB - 1) / TB, TB>>>(hB, agg);
    k_transform<64, false><<<GRID_T, TB>>>(agg, hB, Wn2, bn2, Wr2, hA);
    // predictor head
    k_head<<<GRID_T, TB>>>(hA, Wp1, bp1, Wp2, bp2, out);
}

// round 3
// speedup vs baseline: 1.6429x; 1.6429x over previous
#include <cuda_runtime.h>
#include <math.h>

#define NN 100000
#define NE 1600000
#define NPB 64              // nodes per block group
#define STRD 68             // padded transposed-feature stride (NPB+4, multiple of 4)

// ---------------- scratch (static __device__ — no allocations) ----------------
__device__ int g_deg[NN];
__device__ int g_start[NN];
__device__ int g_cursor[NN];
__device__ int g_csr[NE];
__device__ int g_bsum[128];
__device__ float g_hA[NN * 64];
__device__ float g_hB[NN * 64];
__device__ float g_Wn2p[64 * 64];   // Wn2 @ Wp1
__device__ float g_Wr2p[64 * 64];   // Wr2 @ Wp1
__device__ float g_bp[64];          // bn2 @ Wp1 + bp1

// ---------------- CSR build ----------------
__global__ void k_zero_deg() {
    int i = blockIdx.x * blockDim.x + threadIdx.x;
    if (i < NN) g_deg[i] = 0;
}

__global__ void k_count(const int* __restrict__ dst) {
    int e = blockIdx.x * blockDim.x + threadIdx.x;
    if (e < NE) atomicAdd(&g_deg[dst[e]], 1);
}

__global__ void k_scan_local() {
    __shared__ int s[1024];
    int tid = threadIdx.x;
    int i = blockIdx.x * 1024 + tid;
    int v = (i < NN) ? g_deg[i] : 0;
    s[tid] = v;
    __syncthreads();
    for (int off = 1; off < 1024; off <<= 1) {
        int t = (tid >= off) ? s[tid - off] : 0;
        __syncthreads();
        s[tid] += t;
        __syncthreads();
    }
    if (i < NN) g_start[i] = s[tid] - v;
    if (tid == 1023) g_bsum[blockIdx.x] = s[1023];
}

__global__ void k_scan_bsum(int nb) {
    __shared__ int s[128];
    int tid = threadIdx.x;
    int v = (tid < nb) ? g_bsum[tid] : 0;
    s[tid] = v;
    __syncthreads();
    for (int off = 1; off < 128; off <<= 1) {
        int t = (tid >= off) ? s[tid - off] : 0;
        __syncthreads();
        s[tid] += t;
        __syncthreads();
    }
    if (tid < nb) g_bsum[tid] = s[tid] - v;   // exclusive
}

__global__ void k_scan_add() {
    int i = blockIdx.x * blockDim.x + threadIdx.x;
    if (i < NN) {
        int s = g_start[i] + g_bsum[i >> 10];
        g_start[i] = s;
        g_cursor[i] = s;
    }
}

__global__ void k_fill(const int* __restrict__ src, const int* __restrict__ dst) {
    int e = blockIdx.x * blockDim.x + threadIdx.x;
    if (e < NE) {
        int d = dst[e];
        int p = atomicAdd(&g_cursor[d], 1);
        g_csr[p] = src[e];
    }
}

// ---------------- fuse layer2 weights with head layer1 ----------------
// block 0: g_Wn2p = Wn2 @ Wp1, g_bp = bn2 @ Wp1 + bp1
// block 1: g_Wr2p = Wr2 @ Wp1
__global__ __launch_bounds__(256) void k_fuse_w(const float* __restrict__ Wn2,
                                                const float* __restrict__ Wr2,
                                                const float* __restrict__ bn2,
                                                const float* __restrict__ Wp1,
                                                const float* __restrict__ bp1) {
    __shared__ __align__(16) float sWp[64 * 64];
    __shared__ __align__(16) float sS[64 * 64];
    int tid = threadIdx.x;
    const float* S = (blockIdx.x == 0) ? Wn2 : Wr2;
    float* D = (blockIdx.x == 0) ? g_Wn2p : g_Wr2p;
    for (int idx = tid; idx < 4096; idx += 256) { sWp[idx] = Wp1[idx]; sS[idx] = S[idx]; }
    __syncthreads();
    // thread computes 4 output quads: rows k = tid>>2 spread, cols quad = tid&3? simpler:
    // 1024 float4 outputs over 256 threads -> 4 each
    for (int q = tid; q < 1024; q += 256) {
        int k = q >> 4;          // row 0..63
        int p4 = (q & 15) * 4;   // col quad
        float4 acc = make_float4(0.f, 0.f, 0.f, 0.f);
#pragma unroll
        for (int o = 0; o < 64; o++) {
            float s = sS[k * 64 + o];
            float4 w = *(const float4*)&sWp[o * 64 + p4];
            acc.x += s * w.x; acc.y += s * w.y; acc.z += s * w.z; acc.w += s * w.w;
        }
        *(float4*)&D[k * 64 + p4] = acc;
    }
    if (blockIdx.x == 0 && tid < 64) {
        float acc = bp1[tid];
#pragma unroll
        for (int o = 0; o < 64; o++) acc += bn2[o] * sWp[o * 64 + tid];
        g_bp[tid] = acc;
    }
}

// ---------------- fused gather + SAGE transform ----------------
// MODE 0: hout[n][64] = relu(agg@Wn + bn + hin@Wr)
// MODE 1: out[n] = sigmoid( relu(agg@Wn + bn + hin@Wr) . w2 + b2 )   (fused layer2+head)
template <int DIN, int MODE>
__global__ __launch_bounds__(256, 3) void k_layer(const float* __restrict__ hin,
                                                  const float* __restrict__ Wn,
                                                  const float* __restrict__ bn,
                                                  const float* __restrict__ Wr,
                                                  float* __restrict__ hout,
                                                  const float* __restrict__ w2,
                                                  const float* __restrict__ b2p) {
    extern __shared__ __align__(16) float smem[];
    float* sWn = smem;                       // DIN*64
    float* sWr = sWn + DIN * 64;             // DIN*64
    float* sbn = sWr + DIN * 64;             // 64
    float* sA  = sbn + 64;                   // DIN*STRD (transposed agg)
    float* sH  = sA + DIN * STRD;            // DIN*STRD (transposed root)

    __shared__ __align__(16) float sP[64 * 17];
    __shared__ float sw2[64];

    int tid = threadIdx.x;
    // stage weights
    for (int idx = tid; idx < DIN * 64; idx += 256) { sWn[idx] = Wn[idx]; sWr[idx] = Wr[idx]; }
    if (tid < 64) {
        sbn[tid] = bn[tid];
        if (MODE == 1) sw2[tid] = w2[tid];
    }

    // ---- gather phase: 4 threads per node ----
    constexpr int CROW = DIN / 4;     // float4 chunks per row (8 or 16)
    constexpr int CPT  = CROW / 4;    // chunks per thread (2 or 4)
    int base = blockIdx.x * NPB;
    int nloc = tid >> 2;
    int q = tid & 3;
    int n = base + nloc;
    bool valid = (n < NN);

    float4 acc[CPT];
#pragma unroll
    for (int j = 0; j < CPT; j++) acc[j] = make_float4(0.f, 0.f, 0.f, 0.f);

    int st = 0, dg = 0;
    if (valid) { st = g_start[n]; dg = g_deg[n]; }
    const float4* h4 = (const float4*)hin;
#pragma unroll 2
    for (int i = st; i < st + dg; i++) {
        int s = __ldg(&g_csr[i]);
#pragma unroll
        for (int j = 0; j < CPT; j++) {
            float4 v = h4[s * CROW + q + 4 * j];
            acc[j].x += v.x; acc[j].y += v.y; acc[j].z += v.z; acc[j].w += v.w;
        }
    }
    float inv = (dg > 0) ? 1.f / (float)dg : 0.f;

    float4 rt[CPT];
#pragma unroll
    for (int j = 0; j < CPT; j++) rt[j] = make_float4(0.f, 0.f, 0.f, 0.f);
    if (valid) {
#pragma unroll
        for (int j = 0; j < CPT; j++) rt[j] = h4[n * CROW + q + 4 * j];
    }

    // transposed store into shared
#pragma unroll
    for (int j = 0; j < CPT; j++) {
        int k0 = 4 * (q + 4 * j);
        sA[(k0 + 0) * STRD + nloc] = acc[j].x * inv;
        sA[(k0 + 1) * STRD + nloc] = acc[j].y * inv;
        sA[(k0 + 2) * STRD + nloc] = acc[j].z * inv;
        sA[(k0 + 3) * STRD + nloc] = acc[j].w * inv;
        sH[(k0 + 0) * STRD + nloc] = rt[j].x;
        sH[(k0 + 1) * STRD + nloc] = rt[j].y;
        sH[(k0 + 2) * STRD + nloc] = rt[j].z;
        sH[(k0 + 3) * STRD + nloc] = rt[j].w;
    }
    __syncthreads();

    // ---- transform phase: 4 nodes x 4 outputs per thread ----
    int nq = tid >> 4;   // 0..15 : node quad
    int oq = tid & 15;   // 0..15 : output quad
    float4 bias = *(const float4*)&sbn[oq * 4];
    float c00 = bias.x, c01 = bias.y, c02 = bias.z, c03 = bias.w;
    float c10 = bias.x, c11 = bias.y, c12 = bias.z, c13 = bias.w;
    float c20 = bias.x, c21 = bias.y, c22 = bias.z, c23 = bias.w;
    float c30 = bias.x, c31 = bias.y, c32 = bias.z, c33 = bias.w;

#pragma unroll
    for (int k = 0; k < DIN; k++) {
        float4 a = *(const float4*)&sA[k * STRD + 4 * nq];
        float4 h = *(const float4*)&sH[k * STRD + 4 * nq];
        float4 wn = *(const float4*)&sWn[k * 64 + 4 * oq];
        float4 wr = *(const float4*)&sWr[k * 64 + 4 * oq];
        c00 += a.x * wn.x; c01 += a.x * wn.y; c02 += a.x * wn.z; c03 += a.x * wn.w;
        c10 += a.y * wn.x; c11 += a.y * wn.y; c12 += a.y * wn.z; c13 += a.y * wn.w;
        c20 += a.z * wn.x; c21 += a.z * wn.y; c22 += a.z * wn.z; c23 += a.z * wn.w;
        c30 += a.w * wn.x; c31 += a.w * wn.y; c32 += a.w * wn.z; c33 += a.w * wn.w;
        c00 += h.x * wr.x; c01 += h.x * wr.y; c02 += h.x * wr.z; c03 += h.x * wr.w;
        c10 += h.y * wr.x; c11 += h.y * wr.y; c12 += h.y * wr.z; c13 += h.y * wr.w;
        c20 += h.z * wr.x; c21 += h.z * wr.y; c22 += h.z * wr.z; c23 += h.z * wr.w;
        c30 += h.w * wr.x; c31 += h.w * wr.y; c32 += h.w * wr.z; c33 += h.w * wr.w;
    }

    if (MODE == 0) {
        // relu + store float4 per node
        float4* ho4 = (float4*)hout;
        int n0 = base + 4 * nq;
        float r[4][4] = {{c00,c01,c02,c03},{c10,c11,c12,c13},{c20,c21,c22,c23},{c30,c31,c32,c33}};
#pragma unroll
        for (int i = 0; i < 4; i++) {
            int node = n0 + i;
            if (node < NN) {
                float4 o;
                o.x = fmaxf(r[i][0], 0.f); o.y = fmaxf(r[i][1], 0.f);
                o.z = fmaxf(r[i][2], 0.f); o.w = fmaxf(r[i][3], 0.f);
                ho4[node * 16 + oq] = o;
            }
        }
    } else {
        // relu, dot with w2 chunk, cross-thread reduce, sigmoid
        float4 w = *(const float4*)&sw2[oq * 4];
        float r[4][4] = {{c00,c01,c02,c03},{c10,c11,c12,c13},{c20,c21,c22,c23},{c30,c31,c32,c33}};
#pragma unroll
        for (int i = 0; i < 4; i++) {
            float p = fmaxf(r[i][0], 0.f) * w.x + fmaxf(r[i][1], 0.f) * w.y
                    + fmaxf(r[i][2], 0.f) * w.z + fmaxf(r[i][3], 0.f) * w.w;
            sP[(4 * nq + i) * 17 + oq] = p;
        }
        __syncthreads();
        if (tid < 64) {
            int node = base + tid;
            if (node < NN) {
                float s = 0.f;
#pragma unroll
                for (int j = 0; j < 16; j++) s += sP[tid * 17 + j];
                s += b2p[0];
                hout[node] = 1.f / (1.f + expf(-s));
            }
        }
    }
}

// ---------------- launch ----------------
extern "C" void kernel_launch(void* const* d_in, const int* in_sizes, int n_in,
                              void* d_out, int out_size) {
    const float* x   = (const float*)d_in[0];
    const int*   ei  = (const int*)d_in[1];
    const int*   src = ei;
    const int*   dst = ei + NE;
    const float* Wn0 = (const float*)d_in[2];
    const float* bn0 = (const float*)d_in[3];
    const float* Wr0 = (const float*)d_in[4];
    const float* Wn1 = (const float*)d_in[5];
    const float* bn1 = (const float*)d_in[6];
    const float* Wr1 = (const float*)d_in[7];
    const float* Wn2 = (const float*)d_in[8];
    const float* bn2 = (const float*)d_in[9];
    const float* Wr2 = (const float*)d_in[10];
    const float* Wp1 = (const float*)d_in[11];
    const float* bp1 = (const float*)d_in[12];
    const float* Wp2 = (const float*)d_in[13];
    const float* bp2 = (const float*)d_in[14];
    float* out = (float*)d_out;

    float* hA;   cudaGetSymbolAddress((void**)&hA,   g_hA);
    float* hB;   cudaGetSymbolAddress((void**)&hB,   g_hB);
    float* Wn2p; cudaGetSymbolAddress((void**)&Wn2p, g_Wn2p);
    float* Wr2p; cudaGetSymbolAddress((void**)&Wr2p, g_Wr2p);
    float* bpf;  cudaGetSymbolAddress((void**)&bpf,  g_bp);

    // dynamic smem sizes
    const int SM32 = (2 * 32 * 64 + 64 + 2 * 32 * STRD) * 4;   // ~34 KB
    const int SM64 = (2 * 64 * 64 + 64 + 2 * 64 * STRD) * 4;   // ~66.3 KB
    cudaFuncSetAttribute(k_layer<64, 0>, cudaFuncAttributeMaxDynamicSharedMemorySize, SM64);
    cudaFuncSetAttribute(k_layer<64, 1>, cudaFuncAttributeMaxDynamicSharedMemorySize, SM64);

    const int TB = 256;
    const int NGROUPS = (NN + NPB - 1) / NPB;   // 1563

    // CSR build
    k_zero_deg<<<(NN + TB - 1) / TB, TB>>>();
    k_count<<<(NE + TB - 1) / TB, TB>>>(dst);
    k_scan_local<<<(NN + 1023) / 1024, 1024>>>();
    k_scan_bsum<<<1, 128>>>((NN + 1023) / 1024);
    k_scan_add<<<(NN + TB - 1) / TB, TB>>>();
    k_fill<<<(NE + TB - 1) / TB, TB>>>(src, dst);

    // fused (Wn2@Wp1, Wr2@Wp1, bn2@Wp1+bp1)
    k_fuse_w<<<2, 256>>>(Wn2, Wr2, bn2, Wp1, bp1);

    // layer 0: IN=32 -> 64, relu
    k_layer<32, 0><<<NGROUPS, TB, SM32>>>(x, Wn0, bn0, Wr0, hA, nullptr, nullptr);
    // layer 1: 64 -> 64, relu
    k_layer<64, 0><<<NGROUPS, TB, SM64>>>(hA, Wn1, bn1, Wr1, hB, nullptr, nullptr);
    // layer 2 + head (fused): sigmoid(relu(agg@Wn2p + h@Wr2p + bp) . Wp2 + bp2)
    k_layer<64, 1><<<NGROUPS, TB, SM64>>>(hB, Wn2p, bpf, Wr2p, out, Wp2, bp2);
}